// round 12
// baseline (speedup 1.0000x reference)
#include <cuda_runtime.h>
#include <cuda_fp16.h>
#include <math.h>
#include <stdint.h>

// Problem constants
#define BATCH 2
#define S_LEN 2048
#define HID   1024
#define NH    16
#define DH    64
#define MTOT (BATCH * S_LEN)   // 4096
#define LOG2E 1.4426950408889634f

// Scratch (allocation-free rule: __device__ globals)
__device__ __half g_qkv_h[(size_t)MTOT * 3 * HID];
__device__ __half g_vt_h[(size_t)BATCH * NH * DH * S_LEN];    // V^T [b,h,d,s]
__device__ __half g_att_h[(size_t)MTOT * HID];
__device__ __half g_x_h[(size_t)MTOT * HID];
__device__ __half g_wqkv_h[(size_t)3 * HID * HID];
__device__ __half g_wout_h[(size_t)HID * HID];

__device__ __forceinline__ uint32_t smem_u32(const void* p) {
    uint32_t a;
    asm("{ .reg .u64 t; cvta.to.shared.u64 t, %1; cvt.u32.u64 %0, t; }"
        : "=r"(a) : "l"(p));
    return a;
}

// e^x via FMA-pipe exp2 polynomial (no MUFU). Valid x <= 0 (clamped below).
__device__ __forceinline__ float expe(float x) {
    float t = fmaxf(x * LOG2E, -126.0f);
    float z = t + 12582912.0f;
    int ei = __float_as_int(z) - 0x4B400000;
    float f = t - (float)ei;
    float p = 1.3333558146e-3f;
    p = fmaf(p, f, 9.6181291057e-3f);
    p = fmaf(p, f, 5.5504108664e-2f);
    p = fmaf(p, f, 2.4022650695e-1f);
    p = fmaf(p, f, 6.9314718056e-1f);
    p = fmaf(p, f, 1.0f);
    return p * __int_as_float((ei + 127) << 23);
}

__device__ __forceinline__ void mma_f16(float* c, const uint32_t* a,
                                        const uint32_t* b) {
    asm volatile(
        "mma.sync.aligned.m16n8k16.row.col.f32.f16.f16.f32 "
        "{%0,%1,%2,%3}, {%4,%5,%6,%7}, {%8,%9}, {%0,%1,%2,%3};"
        : "+f"(c[0]), "+f"(c[1]), "+f"(c[2]), "+f"(c[3])
        : "r"(a[0]), "r"(a[1]), "r"(a[2]), "r"(a[3]), "r"(b[0]), "r"(b[1]));
}
__device__ __forceinline__ void ldm_x4(uint32_t* r, uint32_t addr) {
    asm volatile(
        "ldmatrix.sync.aligned.m8n8.x4.shared.b16 {%0,%1,%2,%3}, [%4];"
        : "=r"(r[0]), "=r"(r[1]), "=r"(r[2]), "=r"(r[3]) : "r"(addr));
}
__device__ __forceinline__ uint32_t packh2(float a, float b) {
    __half2 h = __floats2half2_rn(a, b);
    return *reinterpret_cast<uint32_t*>(&h);
}

// ---------------------------------------------------------------------------
// fused fp16 conversion prepass (one launch for x, w_qkv, w_out)
// ---------------------------------------------------------------------------
#define NX (MTOT * HID)            // 4194304
#define NWQ (3 * HID * HID)        // 3145728
#define NWO (HID * HID)            // 1048576

__global__ __launch_bounds__(256) void conv_all_kernel(
    const float* __restrict__ x, const float* __restrict__ wq,
    const float* __restrict__ wo, __half* __restrict__ xh,
    __half* __restrict__ wqh, __half* __restrict__ woh)
{
    int i = (blockIdx.x * 256 + threadIdx.x) * 4;
    const float* src;
    __half* dst;
    if (i < NX) {
        src = x + i; dst = xh + i;
    } else if (i < NX + NWQ) {
        src = wq + (i - NX); dst = wqh + (i - NX);
    } else {
        src = wo + (i - NX - NWQ); dst = woh + (i - NX - NWQ);
    }
    float4 v = *(const float4*)src;
    *(__half2*)dst = __floats2half2_rn(v.x, v.y);
    *(__half2*)(dst + 2) = __floats2half2_rn(v.z, v.w);
}

// ---------------------------------------------------------------------------
// fp16 mma.sync GEMM. CTA 128x128, BK=64 halves, 256 threads, warp 64x32,
// 3-stage cp.async, pipelined ldmatrix. V region written transposed+coalesced.
// ---------------------------------------------------------------------------
#define BM 128
#define BN 128
#define BKH 64
#define BKP 72
#define NSTAGE 3
#define STAGEH (BM * BKP)

__global__ __launch_bounds__(256, 2) void gemm_h_kernel(
    const __half* __restrict__ A, const __half* __restrict__ B,
    const float* __restrict__ bias, float* __restrict__ Cf,
    __half* __restrict__ Ch, __half* __restrict__ vt,
    int M, int N, int K, int mode)
{
    extern __shared__ __half smh[];
    __half* As = smh;
    __half* Bs = smh + NSTAGE * STAGEH;

    const int tid = threadIdx.x;
    const int wid = tid >> 5;
    const int lane = tid & 31;
    const int g = lane >> 2;
    const int tig = lane & 3;
    const int ri = lane & 7;
    const int tq = lane >> 3;
    const int wm = wid & 1;
    const int wn = wid >> 1;
    const int m0 = blockIdx.y * BM;
    const int n0 = blockIdx.x * BN;

    const int lrow = tid & 127;
    const int isB = tid >> 7;
    const __half* Rg = (isB ? B + (size_t)(n0 + lrow) * K
                            : A + (size_t)(m0 + lrow) * K);
    const uint32_t rDst = smem_u32((isB ? Bs : As) + lrow * BKP);

    const uint32_t aLane = (uint32_t)(((tq & 1) * 8 + ri) * 144) + (tq >> 1) * 16;
    const uint32_t bLane = (uint32_t)(((tq >> 1) * 8 + ri) * 144) + (tq & 1) * 16;
    const uint32_t aBase0 = smem_u32(As) + (uint32_t)(wm * 64 * 144) + aLane;
    const uint32_t bBase0 = smem_u32(Bs) + (uint32_t)(wn * 32 * 144) + bLane;

    float acc[4][4][4];
#pragma unroll
    for (int mf = 0; mf < 4; mf++)
#pragma unroll
        for (int nf = 0; nf < 4; nf++)
#pragma unroll
            for (int r = 0; r < 4; r++) acc[mf][nf][r] = 0.0f;

    const int NT = K / BKH;

#define ISSUE_STAGE(s, kt) do { \
    uint32_t _d = rDst + (s) * (STAGEH * 2); \
    const __half* _p = Rg + (kt) * BKH; \
    _Pragma("unroll") \
    for (int _i = 0; _i < 8; _i++) { \
        asm volatile("cp.async.cg.shared.global [%0], [%1], 16;" \
                     :: "r"(_d + _i * 16), "l"(_p + _i * 8)); \
    } \
    asm volatile("cp.async.commit_group;"); \
} while (0)

#define LOAD_FRAGS(buf, aB, bB, ks) do { \
    _Pragma("unroll") \
    for (int _mf = 0; _mf < 4; _mf++) \
        ldm_x4(af[buf][_mf], (aB) + (uint32_t)(_mf * 16 * 144) + (ks) * 32); \
    _Pragma("unroll") \
    for (int _np = 0; _np < 2; _np++) \
        ldm_x4(bf[buf][_np], (bB) + (uint32_t)(_np * 16 * 144) + (ks) * 32); \
} while (0)

    ISSUE_STAGE(0, 0);
    ISSUE_STAGE(1, 1);

    uint32_t af[2][4][4];
    uint32_t bf[2][2][4];

    int stage = 0;
    for (int kt = 0; kt < NT; kt++) {
        if (kt == NT - 1) {
            asm volatile("cp.async.wait_group 0;");
        } else {
            asm volatile("cp.async.wait_group 1;");
        }
        __syncthreads();

        if (kt + 2 < NT) {
            int s2 = stage + 2; if (s2 >= NSTAGE) s2 -= NSTAGE;
            ISSUE_STAGE(s2, kt + 2);
        }

        const uint32_t aB = aBase0 + (uint32_t)stage * (STAGEH * 2);
        const uint32_t bB = bBase0 + (uint32_t)stage * (STAGEH * 2);

        LOAD_FRAGS(0, aB, bB, 0);
#pragma unroll
        for (int ks = 0; ks < 4; ks++) {
            const int cur = ks & 1;
            if (ks < 3) LOAD_FRAGS(cur ^ 1, aB, bB, ks + 1);
#pragma unroll
            for (int mf = 0; mf < 4; mf++)
#pragma unroll
                for (int nf = 0; nf < 4; nf++)
                    mma_f16(acc[mf][nf], af[cur][mf],
                            &bf[cur][nf >> 1][(nf & 1) * 2]);
        }

        stage = stage + 1; if (stage >= NSTAGE) stage -= NSTAGE;
    }

    if (mode == 1 && n0 >= 2 * HID) {
        // ---- V region: transpose via smem, coalesced 16B stores to vt ----
        __syncthreads();   // stage buffers dead; reuse as transpose scratch
        __half* ts = smh + wid * (32 * 72);
#pragma unroll
        for (int mf = 0; mf < 4; mf++) {
            const int sl0 = mf * 16 + g;
#pragma unroll
            for (int nf = 0; nf < 4; nf++) {
                const int dl = nf * 8 + 2 * tig;
                ts[dl * 72 + sl0]       = __float2half_rn(acc[mf][nf][0]);
                ts[(dl + 1) * 72 + sl0] = __float2half_rn(acc[mf][nf][1]);
                ts[dl * 72 + sl0 + 8]       = __float2half_rn(acc[mf][nf][2]);
                ts[(dl + 1) * 72 + sl0 + 8] = __float2half_rn(acc[mf][nf][3]);
            }
        }
        __syncwarp();
        const int vh0 = (n0 - 2 * HID) + wn * 32;
        const int srow = m0 + wm * 64;
        const int bb = srow >> 11;
        const int sbase = srow & 2047;
#pragma unroll
        for (int pass = 0; pass < 8; pass++) {
            const int r = pass * 4 + (lane >> 3);
            const int cc = (lane & 7) * 8;
            uint4 v = *(uint4*)(ts + r * 72 + cc);
            __half* dst = vt + ((size_t)(bb * NH) << 17) +
                          (size_t)(vh0 + r) * S_LEN + sbase + cc;
            *(uint4*)dst = v;
        }
    } else {
#pragma unroll
        for (int mf = 0; mf < 4; mf++) {
            const int row0 = m0 + wm * 64 + mf * 16 + g;
#pragma unroll
            for (int nf = 0; nf < 4; nf++) {
                const int col = n0 + wn * 32 + nf * 8 + 2 * tig;
                float v00 = acc[mf][nf][0], v01 = acc[mf][nf][1];
                float v10 = acc[mf][nf][2], v11 = acc[mf][nf][3];
                if (mode == 0) {
                    float b0 = bias ? bias[col] : 0.0f;
                    float b1 = bias ? bias[col + 1] : 0.0f;
                    float2 w0 = {v00 + b0, v01 + b1};
                    float2 w1 = {v10 + b0, v11 + b1};
                    *(float2*)(Cf + (size_t)row0 * N + col) = w0;
                    *(float2*)(Cf + (size_t)(row0 + 8) * N + col) = w1;
                } else {
                    *(__half2*)(Ch + (size_t)row0 * N + col) =
                        __floats2half2_rn(v00, v01);
                    *(__half2*)(Ch + (size_t)(row0 + 8) * N + col) =
                        __floats2half2_rn(v10, v11);
                }
            }
        }
    }
}

// ---------------------------------------------------------------------------
// fp16 flash attention. CTA = 128 queries of one (b,h), 256 threads (8 warps).
// Q in regs (pre-scaled by exact 0.125); P packed register-direct from QK
// C-fragments (no P smem). K/Vt double-buffered cp.async.
// ---------------------------------------------------------------------------
#define LDH 72
#define SM_Q 0
#define SM_QSZ (128 * LDH)
#define SM_K SM_QSZ
#define SM_KSZ (64 * LDH)
#define SM_V (SM_K + 2 * SM_KSZ)
#define SM_VSZ (64 * LDH)
#define SMEM_ATT ((SM_V + 2 * SM_VSZ) * 2)   // 55296 bytes

__global__ __launch_bounds__(256, 2) void attn_h_kernel(
    const __half* __restrict__ qkv, const __half* __restrict__ vtg,
    __half* __restrict__ outp)
{
    extern __shared__ __half smh[];
    const int tid = threadIdx.x;
    const int lane = tid & 31;
    const int wid = tid >> 5;
    const int g = lane >> 2;
    const int tig = lane & 3;
    const int ri = lane & 7;
    const int tq = lane >> 3;
    const int bh = blockIdx.y;
    const int b = bh >> 4;
    const int h = bh & 15;
    const int q0 = blockIdx.x * 128;

    const __half* qbase = qkv + (size_t)b * S_LEN * 3 * HID + h * DH;
    const __half* vbase = vtg + ((size_t)bh) * DH * S_LEN;

#define LOAD_KV(kt, buf) do { \
    _Pragma("unroll") \
    for (int _i = 0; _i < 2; _i++) { \
        int _t = tid + _i * 256; \
        int _r = _t >> 3, _c = (_t & 7) * 8; \
        const __half* _sk = qbase + (size_t)((kt) * 64 + _r) * 3 * HID + HID + _c; \
        asm volatile("cp.async.cg.shared.global [%0], [%1], 16;" \
            :: "r"(smem_u32(smh + SM_K + (buf) * SM_KSZ + _r * LDH + _c)), "l"(_sk)); \
        const __half* _sv = vbase + (size_t)_r * S_LEN + (kt) * 64 + _c; \
        asm volatile("cp.async.cg.shared.global [%0], [%1], 16;" \
            :: "r"(smem_u32(smh + SM_V + (buf) * SM_VSZ + _r * LDH + _c)), "l"(_sv)); \
    } \
} while (0)

    // stage Q (128 rows), then K0/V0, K1/V1
#pragma unroll
    for (int i = 0; i < 4; i++) {
        int t = tid + i * 256;
        int r = t >> 3, c = (t & 7) * 8;
        const __half* sq = qbase + (size_t)(q0 + r) * 3 * HID + c;
        asm volatile("cp.async.cg.shared.global [%0], [%1], 16;"
            :: "r"(smem_u32(smh + SM_Q + r * LDH + c)), "l"(sq));
    }
    asm volatile("cp.async.commit_group;");
    LOAD_KV(0, 0);
    asm volatile("cp.async.commit_group;");
    LOAD_KV(1, 1);
    asm volatile("cp.async.commit_group;");

    const uint32_t aLane = (uint32_t)(((tq & 1) * 8 + ri) * 144) + (tq >> 1) * 16;
    const uint32_t bLane = (uint32_t)(((tq >> 1) * 8 + ri) * 144) + (tq & 1) * 16;
    const uint32_t qAddr = smem_u32(smh + SM_Q + (wid * 16) * LDH) + aLane;

    asm volatile("cp.async.wait_group 2;");
    __syncthreads();
    uint32_t qf[4][4];
#pragma unroll
    for (int ks = 0; ks < 4; ks++) ldm_x4(qf[ks], qAddr + ks * 32);
    {   // exact fp16 scale by 0.125 (power of two: no rounding error)
        const __half2 sc = __float2half2_rn(0.125f);
#pragma unroll
        for (int ks = 0; ks < 4; ks++)
#pragma unroll
            for (int r = 0; r < 4; r++) {
                __half2 t = *reinterpret_cast<__half2*>(&qf[ks][r]);
                t = __hmul2(t, sc);
                qf[ks][r] = *reinterpret_cast<uint32_t*>(&t);
            }
    }

    float m0 = -1e30f, m1 = -1e30f, l0 = 0.0f, l1 = 0.0f;
    float oacc[8][4];
#pragma unroll
    for (int nf = 0; nf < 8; nf++)
#pragma unroll
        for (int r = 0; r < 4; r++) oacc[nf][r] = 0.0f;

    for (int kt = 0; kt < S_LEN / 64; kt++) {
        asm volatile("cp.async.wait_group 1;");
        __syncthreads();
        const uint32_t kAddr =
            smem_u32(smh + SM_K + (kt & 1) * SM_KSZ) + bLane;
        const uint32_t vAddr =
            smem_u32(smh + SM_V + (kt & 1) * SM_VSZ) + bLane;

        // ---- S = (Q/8) K^T (pipelined kfr) ----
        float sacc[8][4];
#pragma unroll
        for (int nf = 0; nf < 8; nf++)
#pragma unroll
            for (int r = 0; r < 4; r++) sacc[nf][r] = 0.0f;

        {
            uint32_t kfr[2][4];
            ldm_x4(kfr[0], kAddr);
#pragma unroll
            for (int idx = 0; idx < 16; idx++) {
                const int ks = idx >> 2, np = idx & 3;
                if (idx < 15) {
                    const int nks = (idx + 1) >> 2, nnp = (idx + 1) & 3;
                    ldm_x4(kfr[(idx + 1) & 1],
                           kAddr + (uint32_t)(nnp * 16 * 144) + nks * 32);
                }
                mma_f16(sacc[2 * np], qf[ks], kfr[idx & 1]);
                mma_f16(sacc[2 * np + 1], qf[ks], kfr[idx & 1] + 2);
            }
        }

        // ---- online softmax (rows g, g+8); exp in place ----
        float rmax0 = -1e30f, rmax1 = -1e30f;
#pragma unroll
        for (int nf = 0; nf < 8; nf++) {
            rmax0 = fmaxf(rmax0, fmaxf(sacc[nf][0], sacc[nf][1]));
            rmax1 = fmaxf(rmax1, fmaxf(sacc[nf][2], sacc[nf][3]));
        }
        rmax0 = fmaxf(rmax0, __shfl_xor_sync(0xffffffffu, rmax0, 1));
        rmax0 = fmaxf(rmax0, __shfl_xor_sync(0xffffffffu, rmax0, 2));
        rmax1 = fmaxf(rmax1, __shfl_xor_sync(0xffffffffu, rmax1, 1));
        rmax1 = fmaxf(rmax1, __shfl_xor_sync(0xffffffffu, rmax1, 2));

        const float mn0 = fmaxf(m0, rmax0);
        const float mn1 = fmaxf(m1, rmax1);
        const float corr0 = expe(m0 - mn0);
        const float corr1 = expe(m1 - mn1);
        m0 = mn0; m1 = mn1;

        float s0 = 0.0f, s1 = 0.0f;
#pragma unroll
        for (int nf = 0; nf < 8; nf++) {
            sacc[nf][0] = expe(sacc[nf][0] - mn0);
            sacc[nf][1] = expe(sacc[nf][1] - mn0);
            sacc[nf][2] = expe(sacc[nf][2] - mn1);
            sacc[nf][3] = expe(sacc[nf][3] - mn1);
            s0 += sacc[nf][0] + sacc[nf][1];
            s1 += sacc[nf][2] + sacc[nf][3];
        }
        s0 += __shfl_xor_sync(0xffffffffu, s0, 1);
        s0 += __shfl_xor_sync(0xffffffffu, s0, 2);
        s1 += __shfl_xor_sync(0xffffffffu, s1, 1);
        s1 += __shfl_xor_sync(0xffffffffu, s1, 2);
        l0 = l0 * corr0 + s0;
        l1 = l1 * corr1 + s1;
#pragma unroll
        for (int nf = 0; nf < 8; nf++) {
            oacc[nf][0] *= corr0; oacc[nf][1] *= corr0;
            oacc[nf][2] *= corr1; oacc[nf][3] *= corr1;
        }

        // ---- pack P directly: QK C-frag layout == PV A-frag layout ----
        uint32_t pf[4][4];
#pragma unroll
        for (int ks = 0; ks < 4; ks++) {
            pf[ks][0] = packh2(sacc[2 * ks][0], sacc[2 * ks][1]);
            pf[ks][1] = packh2(sacc[2 * ks][2], sacc[2 * ks][3]);
            pf[ks][2] = packh2(sacc[2 * ks + 1][0], sacc[2 * ks + 1][1]);
            pf[ks][3] = packh2(sacc[2 * ks + 1][2], sacc[2 * ks + 1][3]);
        }

        // ---- O += P V (pipelined vfr) ----
        {
            uint32_t vfr[2][4];
            ldm_x4(vfr[0], vAddr);
#pragma unroll
            for (int idx = 0; idx < 16; idx++) {
                const int ks = idx >> 2, np = idx & 3;
                if (idx < 15) {
                    const int nks = (idx + 1) >> 2, nnp = (idx + 1) & 3;
                    ldm_x4(vfr[(idx + 1) & 1],
                           vAddr + (uint32_t)(nnp * 16 * 144) + nks * 32);
                }
                mma_f16(oacc[2 * np], pf[ks], vfr[idx & 1]);
                mma_f16(oacc[2 * np + 1], pf[ks], vfr[idx & 1] + 2);
            }
        }

        __syncthreads();
        if (kt + 2 < S_LEN / 64) LOAD_KV(kt + 2, kt & 1);
        asm volatile("cp.async.commit_group;");
    }

    // ---- epilogue: fp16 out for the out-projection ----
    const float inv0 = 1.0f / l0;
    const float inv1 = 1.0f / l1;
    const int row0 = q0 + wid * 16 + g;
    __half* od = outp + (size_t)(b * S_LEN + row0) * HID + h * DH;
#pragma unroll
    for (int nf = 0; nf < 8; nf++) {
        const int col = nf * 8 + 2 * tig;
        *(__half2*)(od + col) =
            __floats2half2_rn(oacc[nf][0] * inv0, oacc[nf][1] * inv0);
        *(__half2*)(od + (size_t)8 * HID + col) =
            __floats2half2_rn(oacc[nf][2] * inv1, oacc[nf][3] * inv1);
    }
}

// ---------------------------------------------------------------------------
// Launch
// ---------------------------------------------------------------------------
extern "C" void kernel_launch(void* const* d_in, const int* in_sizes, int n_in,
                              void* d_out, int out_size)
{
    const float* x     = (const float*)d_in[0];
    const float* w_qkv = (const float*)d_in[1];
    const float* w_out = (const float*)d_in[2];
    const float* b_out = (const float*)d_in[3];
    float* out = (float*)d_out;

    __half *qkv_p, *vt_p, *att_p, *x_p, *wqkv_p, *wout_p;
    cudaGetSymbolAddress((void**)&qkv_p, g_qkv_h);
    cudaGetSymbolAddress((void**)&vt_p, g_vt_h);
    cudaGetSymbolAddress((void**)&att_p, g_att_h);
    cudaGetSymbolAddress((void**)&x_p, g_x_h);
    cudaGetSymbolAddress((void**)&wqkv_p, g_wqkv_h);
    cudaGetSymbolAddress((void**)&wout_p, g_wout_h);

    const int gemm_smem = NSTAGE * 2 * STAGEH * 2;  // 110592 bytes
    cudaFuncSetAttribute(gemm_h_kernel,
                         cudaFuncAttributeMaxDynamicSharedMemorySize, gemm_smem);
    cudaFuncSetAttribute(attn_h_kernel,
                         cudaFuncAttributeMaxDynamicSharedMemorySize, SMEM_ATT);

    // 0) fused fp32 -> fp16 conversion (one launch)
    conv_all_kernel<<<(NX + NWQ + NWO) / 4 / 256, 256>>>(
        x, w_qkv, w_out, x_p, wqkv_p, wout_p);

    // 1) qkv = x @ w_qkv^T  (q,k -> g_qkv_h; v -> g_vt_h transposed, coalesced)
    gemm_h_kernel<<<dim3(3 * HID / BN, MTOT / BM), 256, gemm_smem>>>(
        x_p, wqkv_p, nullptr, nullptr, qkv_p, vt_p, MTOT, 3 * HID, HID, 1);

    // 2) fp16 flash attention (128-query CTAs, register-direct P)
    attn_h_kernel<<<dim3(S_LEN / 128, BATCH * NH), 256, SMEM_ATT>>>(
        qkv_p, vt_p, att_p);

    // 3) out = att @ w_out^T + b_out  (fp32 output)
    gemm_h_kernel<<<dim3(HID / BN, MTOT / BM), 256, gemm_smem>>>(
        att_p, wout_p, b_out, out, nullptr, nullptr, MTOT, HID, HID, 0);
}

// round 17
// speedup vs baseline: 1.0291x; 1.0291x over previous
#include <cuda_runtime.h>
#include <cuda_fp16.h>
#include <math.h>
#include <stdint.h>

// Problem constants
#define BATCH 2
#define S_LEN 2048
#define HID   1024
#define NH    16
#define DH    64
#define MTOT (BATCH * S_LEN)   // 4096
#define LOG2E 1.4426950408889634f

// Scratch (allocation-free rule: __device__ globals)
__device__ __half g_qkv_h[(size_t)MTOT * 3 * HID];
__device__ __half g_vt_h[(size_t)BATCH * NH * DH * S_LEN];    // V^T [b,h,d,s]
__device__ __half g_att_h[(size_t)MTOT * HID];
__device__ __half g_x_h[(size_t)MTOT * HID];
__device__ __half g_wqkv_h[(size_t)3 * HID * HID];
__device__ __half g_wout_h[(size_t)HID * HID];

__device__ __forceinline__ uint32_t smem_u32(const void* p) {
    uint32_t a;
    asm("{ .reg .u64 t; cvta.to.shared.u64 t, %1; cvt.u32.u64 %0, t; }"
        : "=r"(a) : "l"(p));
    return a;
}

// e^x via FMA-pipe exp2 polynomial (no MUFU).
__device__ __forceinline__ float expe(float x) {
    float t = fmaxf(x * LOG2E, -126.0f);
    float z = t + 12582912.0f;
    int ei = __float_as_int(z) - 0x4B400000;
    float f = t - (float)ei;
    float p = 1.3333558146e-3f;
    p = fmaf(p, f, 9.6181291057e-3f);
    p = fmaf(p, f, 5.5504108664e-2f);
    p = fmaf(p, f, 2.4022650695e-1f);
    p = fmaf(p, f, 6.9314718056e-1f);
    p = fmaf(p, f, 1.0f);
    return p * __int_as_float((ei + 127) << 23);
}

__device__ __forceinline__ void mma_f16(float* c, const uint32_t* a,
                                        const uint32_t* b) {
    asm volatile(
        "mma.sync.aligned.m16n8k16.row.col.f32.f16.f16.f32 "
        "{%0,%1,%2,%3}, {%4,%5,%6,%7}, {%8,%9}, {%0,%1,%2,%3};"
        : "+f"(c[0]), "+f"(c[1]), "+f"(c[2]), "+f"(c[3])
        : "r"(a[0]), "r"(a[1]), "r"(a[2]), "r"(a[3]), "r"(b[0]), "r"(b[1]));
}
__device__ __forceinline__ void ldm_x4(uint32_t* r, uint32_t addr) {
    asm volatile(
        "ldmatrix.sync.aligned.m8n8.x4.shared.b16 {%0,%1,%2,%3}, [%4];"
        : "=r"(r[0]), "=r"(r[1]), "=r"(r[2]), "=r"(r[3]) : "r"(addr));
}
__device__ __forceinline__ uint32_t packh2(float a, float b) {
    __half2 h = __floats2half2_rn(a, b);
    return *reinterpret_cast<uint32_t*>(&h);
}

// ---------------------------------------------------------------------------
// fused fp16 conversion prepass (one launch for x, w_qkv, w_out)
// ---------------------------------------------------------------------------
#define NX (MTOT * HID)
#define NWQ (3 * HID * HID)
#define NWO (HID * HID)

__global__ __launch_bounds__(256) void conv_all_kernel(
    const float* __restrict__ x, const float* __restrict__ wq,
    const float* __restrict__ wo, __half* __restrict__ xh,
    __half* __restrict__ wqh, __half* __restrict__ woh)
{
    int i = (blockIdx.x * 256 + threadIdx.x) * 4;
    const float* src;
    __half* dst;
    if (i < NX) {
        src = x + i; dst = xh + i;
    } else if (i < NX + NWQ) {
        src = wq + (i - NX); dst = wqh + (i - NX);
    } else {
        src = wo + (i - NX - NWQ); dst = woh + (i - NX - NWQ);
    }
    float4 v = *(const float4*)src;
    *(__half2*)dst = __floats2half2_rn(v.x, v.y);
    *(__half2*)(dst + 2) = __floats2half2_rn(v.z, v.w);
}

// ---------------------------------------------------------------------------
// fp16 mma.sync GEMM. CTA 128x128, BK=64 halves, 256 threads, warp 64x32,
// 3-stage cp.async, pipelined ldmatrix. V region written transposed+coalesced.
// ---------------------------------------------------------------------------
#define BM 128
#define BN 128
#define BKH 64
#define BKP 72
#define NSTAGE 3
#define STAGEH (BM * BKP)

__global__ __launch_bounds__(256, 2) void gemm_h_kernel(
    const __half* __restrict__ A, const __half* __restrict__ B,
    const float* __restrict__ bias, float* __restrict__ Cf,
    __half* __restrict__ Ch, __half* __restrict__ vt,
    int M, int N, int K, int mode)
{
    extern __shared__ __half smh[];
    __half* As = smh;
    __half* Bs = smh + NSTAGE * STAGEH;

    const int tid = threadIdx.x;
    const int wid = tid >> 5;
    const int lane = tid & 31;
    const int g = lane >> 2;
    const int tig = lane & 3;
    const int ri = lane & 7;
    const int tq = lane >> 3;
    const int wm = wid & 1;
    const int wn = wid >> 1;
    const int m0 = blockIdx.y * BM;
    const int n0 = blockIdx.x * BN;

    const int lrow = tid & 127;
    const int isB = tid >> 7;
    const __half* Rg = (isB ? B + (size_t)(n0 + lrow) * K
                            : A + (size_t)(m0 + lrow) * K);
    const uint32_t rDst = smem_u32((isB ? Bs : As) + lrow * BKP);

    const uint32_t aLane = (uint32_t)(((tq & 1) * 8 + ri) * 144) + (tq >> 1) * 16;
    const uint32_t bLane = (uint32_t)(((tq >> 1) * 8 + ri) * 144) + (tq & 1) * 16;
    const uint32_t aBase0 = smem_u32(As) + (uint32_t)(wm * 64 * 144) + aLane;
    const uint32_t bBase0 = smem_u32(Bs) + (uint32_t)(wn * 32 * 144) + bLane;

    float acc[4][4][4];
#pragma unroll
    for (int mf = 0; mf < 4; mf++)
#pragma unroll
        for (int nf = 0; nf < 4; nf++)
#pragma unroll
            for (int r = 0; r < 4; r++) acc[mf][nf][r] = 0.0f;

    const int NT = K / BKH;

#define ISSUE_STAGE(s, kt) do { \
    uint32_t _d = rDst + (s) * (STAGEH * 2); \
    const __half* _p = Rg + (kt) * BKH; \
    _Pragma("unroll") \
    for (int _i = 0; _i < 8; _i++) { \
        asm volatile("cp.async.cg.shared.global [%0], [%1], 16;" \
                     :: "r"(_d + _i * 16), "l"(_p + _i * 8)); \
    } \
    asm volatile("cp.async.commit_group;"); \
} while (0)

#define LOAD_FRAGS(buf, aB, bB, ks) do { \
    _Pragma("unroll") \
    for (int _mf = 0; _mf < 4; _mf++) \
        ldm_x4(af[buf][_mf], (aB) + (uint32_t)(_mf * 16 * 144) + (ks) * 32); \
    _Pragma("unroll") \
    for (int _np = 0; _np < 2; _np++) \
        ldm_x4(bf[buf][_np], (bB) + (uint32_t)(_np * 16 * 144) + (ks) * 32); \
} while (0)

    ISSUE_STAGE(0, 0);
    ISSUE_STAGE(1, 1);

    uint32_t af[2][4][4];
    uint32_t bf[2][2][4];

    int stage = 0;
    for (int kt = 0; kt < NT; kt++) {
        if (kt == NT - 1) {
            asm volatile("cp.async.wait_group 0;");
        } else {
            asm volatile("cp.async.wait_group 1;");
        }
        __syncthreads();

        if (kt + 2 < NT) {
            int s2 = stage + 2; if (s2 >= NSTAGE) s2 -= NSTAGE;
            ISSUE_STAGE(s2, kt + 2);
        }

        const uint32_t aB = aBase0 + (uint32_t)stage * (STAGEH * 2);
        const uint32_t bB = bBase0 + (uint32_t)stage * (STAGEH * 2);

        LOAD_FRAGS(0, aB, bB, 0);
#pragma unroll
        for (int ks = 0; ks < 4; ks++) {
            const int cur = ks & 1;
            if (ks < 3) LOAD_FRAGS(cur ^ 1, aB, bB, ks + 1);
#pragma unroll
            for (int mf = 0; mf < 4; mf++)
#pragma unroll
                for (int nf = 0; nf < 4; nf++)
                    mma_f16(acc[mf][nf], af[cur][mf],
                            &bf[cur][nf >> 1][(nf & 1) * 2]);
        }

        stage = stage + 1; if (stage >= NSTAGE) stage -= NSTAGE;
    }

    if (mode == 1 && n0 >= 2 * HID) {
        // ---- V region: transpose via smem, coalesced 16B stores to vt ----
        __syncthreads();
        __half* ts = smh + wid * (32 * 72);
#pragma unroll
        for (int mf = 0; mf < 4; mf++) {
            const int sl0 = mf * 16 + g;
#pragma unroll
            for (int nf = 0; nf < 4; nf++) {
                const int dl = nf * 8 + 2 * tig;
                ts[dl * 72 + sl0]       = __float2half_rn(acc[mf][nf][0]);
                ts[(dl + 1) * 72 + sl0] = __float2half_rn(acc[mf][nf][1]);
                ts[dl * 72 + sl0 + 8]       = __float2half_rn(acc[mf][nf][2]);
                ts[(dl + 1) * 72 + sl0 + 8] = __float2half_rn(acc[mf][nf][3]);
            }
        }
        __syncwarp();
        const int vh0 = (n0 - 2 * HID) + wn * 32;
        const int srow = m0 + wm * 64;
        const int bb = srow >> 11;
        const int sbase = srow & 2047;
#pragma unroll
        for (int pass = 0; pass < 8; pass++) {
            const int r = pass * 4 + (lane >> 3);
            const int cc = (lane & 7) * 8;
            uint4 v = *(uint4*)(ts + r * 72 + cc);
            __half* dst = vt + ((size_t)(bb * NH) << 17) +
                          (size_t)(vh0 + r) * S_LEN + sbase + cc;
            *(uint4*)dst = v;
        }
    } else {
#pragma unroll
        for (int mf = 0; mf < 4; mf++) {
            const int row0 = m0 + wm * 64 + mf * 16 + g;
#pragma unroll
            for (int nf = 0; nf < 4; nf++) {
                const int col = n0 + wn * 32 + nf * 8 + 2 * tig;
                float v00 = acc[mf][nf][0], v01 = acc[mf][nf][1];
                float v10 = acc[mf][nf][2], v11 = acc[mf][nf][3];
                if (mode == 0) {
                    float b0 = bias ? bias[col] : 0.0f;
                    float b1 = bias ? bias[col + 1] : 0.0f;
                    float2 w0 = {v00 + b0, v01 + b1};
                    float2 w1 = {v10 + b0, v11 + b1};
                    *(float2*)(Cf + (size_t)row0 * N + col) = w0;
                    *(float2*)(Cf + (size_t)(row0 + 8) * N + col) = w1;
                } else {
                    *(__half2*)(Ch + (size_t)row0 * N + col) =
                        __floats2half2_rn(v00, v01);
                    *(__half2*)(Ch + (size_t)(row0 + 8) * N + col) =
                        __floats2half2_rn(v10, v11);
                }
            }
        }
    }
}

// ---------------------------------------------------------------------------
// fp16 flash attention. CTA = 64 queries of one (b,h), 128 threads (4 warps),
// 4 CTAs/SM. Q in regs pre-scaled by exact 0.125; P packed register-direct
// (no P smem round-trip). K/Vt double-buffered cp.async.
// ---------------------------------------------------------------------------
#define LDH 72
#define SM_Q 0
#define SM_QSZ (64 * LDH)
#define SM_K SM_QSZ
#define SM_KSZ (64 * LDH)
#define SM_V (SM_K + 2 * SM_KSZ)
#define SM_VSZ (64 * LDH)
#define SMEM_ATT ((SM_V + 2 * SM_VSZ) * 2)   // 46080 bytes

__global__ __launch_bounds__(128, 4) void attn_h_kernel(
    const __half* __restrict__ qkv, const __half* __restrict__ vtg,
    __half* __restrict__ outp)
{
    extern __shared__ __half smh[];
    const int tid = threadIdx.x;
    const int lane = tid & 31;
    const int wid = tid >> 5;
    const int g = lane >> 2;
    const int tig = lane & 3;
    const int ri = lane & 7;
    const int tq = lane >> 3;
    const int bh = blockIdx.y;
    const int b = bh >> 4;
    const int h = bh & 15;
    const int q0 = blockIdx.x * 64;

    const __half* qbase = qkv + (size_t)b * S_LEN * 3 * HID + h * DH;
    const __half* vbase = vtg + ((size_t)bh) * DH * S_LEN;

#define LOAD_KV(kt, buf) do { \
    _Pragma("unroll") \
    for (int _i = 0; _i < 4; _i++) { \
        int _t = tid + _i * 128; \
        int _r = _t >> 3, _c = (_t & 7) * 8; \
        const __half* _sk = qbase + (size_t)((kt) * 64 + _r) * 3 * HID + HID + _c; \
        asm volatile("cp.async.cg.shared.global [%0], [%1], 16;" \
            :: "r"(smem_u32(smh + SM_K + (buf) * SM_KSZ + _r * LDH + _c)), "l"(_sk)); \
        const __half* _sv = vbase + (size_t)_r * S_LEN + (kt) * 64 + _c; \
        asm volatile("cp.async.cg.shared.global [%0], [%1], 16;" \
            :: "r"(smem_u32(smh + SM_V + (buf) * SM_VSZ + _r * LDH + _c)), "l"(_sv)); \
    } \
} while (0)

    // stage Q, then K0/V0, K1/V1
#pragma unroll
    for (int i = 0; i < 4; i++) {
        int t = tid + i * 128;
        int r = t >> 3, c = (t & 7) * 8;
        const __half* sq = qbase + (size_t)(q0 + r) * 3 * HID + c;
        asm volatile("cp.async.cg.shared.global [%0], [%1], 16;"
            :: "r"(smem_u32(smh + SM_Q + r * LDH + c)), "l"(sq));
    }
    asm volatile("cp.async.commit_group;");
    LOAD_KV(0, 0);
    asm volatile("cp.async.commit_group;");
    LOAD_KV(1, 1);
    asm volatile("cp.async.commit_group;");

    const uint32_t aLane = (uint32_t)(((tq & 1) * 8 + ri) * 144) + (tq >> 1) * 16;
    const uint32_t bLane = (uint32_t)(((tq >> 1) * 8 + ri) * 144) + (tq & 1) * 16;
    const uint32_t qAddr = smem_u32(smh + SM_Q + (wid * 16) * LDH) + aLane;

    asm volatile("cp.async.wait_group 2;");
    __syncthreads();
    uint32_t qf[4][4];
#pragma unroll
    for (int ks = 0; ks < 4; ks++) ldm_x4(qf[ks], qAddr + ks * 32);
    {   // exact fp16 scale by 0.125 (power of two)
        const __half2 sc = __float2half2_rn(0.125f);
#pragma unroll
        for (int ks = 0; ks < 4; ks++)
#pragma unroll
            for (int r = 0; r < 4; r++) {
                __half2 t = *reinterpret_cast<__half2*>(&qf[ks][r]);
                t = __hmul2(t, sc);
                qf[ks][r] = *reinterpret_cast<uint32_t*>(&t);
            }
    }

    float m0 = -1e30f, m1 = -1e30f, l0 = 0.0f, l1 = 0.0f;
    float oacc[8][4];
#pragma unroll
    for (int nf = 0; nf < 8; nf++)
#pragma unroll
        for (int r = 0; r < 4; r++) oacc[nf][r] = 0.0f;

    for (int kt = 0; kt < S_LEN / 64; kt++) {
        asm volatile("cp.async.wait_group 1;");
        __syncthreads();
        const uint32_t kAddr =
            smem_u32(smh + SM_K + (kt & 1) * SM_KSZ) + bLane;
        const uint32_t vAddr =
            smem_u32(smh + SM_V + (kt & 1) * SM_VSZ) + bLane;

        // ---- S = (Q/8) K^T (pipelined kfr) ----
        float sacc[8][4];
#pragma unroll
        for (int nf = 0; nf < 8; nf++)
#pragma unroll
            for (int r = 0; r < 4; r++) sacc[nf][r] = 0.0f;

        {
            uint32_t kfr[2][4];
            ldm_x4(kfr[0], kAddr);
#pragma unroll
            for (int idx = 0; idx < 16; idx++) {
                const int ks = idx >> 2, np = idx & 3;
                if (idx < 15) {
                    const int nks = (idx + 1) >> 2, nnp = (idx + 1) & 3;
                    ldm_x4(kfr[(idx + 1) & 1],
                           kAddr + (uint32_t)(nnp * 16 * 144) + nks * 32);
                }
                mma_f16(sacc[2 * np], qf[ks], kfr[idx & 1]);
                mma_f16(sacc[2 * np + 1], qf[ks], kfr[idx & 1] + 2);
            }
        }

        // ---- online softmax (rows g, g+8) ----
        float rmax0 = -1e30f, rmax1 = -1e30f;
#pragma unroll
        for (int nf = 0; nf < 8; nf++) {
            rmax0 = fmaxf(rmax0, fmaxf(sacc[nf][0], sacc[nf][1]));
            rmax1 = fmaxf(rmax1, fmaxf(sacc[nf][2], sacc[nf][3]));
        }
        rmax0 = fmaxf(rmax0, __shfl_xor_sync(0xffffffffu, rmax0, 1));
        rmax0 = fmaxf(rmax0, __shfl_xor_sync(0xffffffffu, rmax0, 2));
        rmax1 = fmaxf(rmax1, __shfl_xor_sync(0xffffffffu, rmax1, 1));
        rmax1 = fmaxf(rmax1, __shfl_xor_sync(0xffffffffu, rmax1, 2));

        const float mn0 = fmaxf(m0, rmax0);
        const float mn1 = fmaxf(m1, rmax1);
        const float corr0 = expe(m0 - mn0);
        const float corr1 = expe(m1 - mn1);
        m0 = mn0; m1 = mn1;

        float s0 = 0.0f, s1 = 0.0f;
#pragma unroll
        for (int nf = 0; nf < 8; nf++) {
            sacc[nf][0] = expe(sacc[nf][0] - mn0);
            sacc[nf][1] = expe(sacc[nf][1] - mn0);
            sacc[nf][2] = expe(sacc[nf][2] - mn1);
            sacc[nf][3] = expe(sacc[nf][3] - mn1);
            s0 += sacc[nf][0] + sacc[nf][1];
            s1 += sacc[nf][2] + sacc[nf][3];
        }
        s0 += __shfl_xor_sync(0xffffffffu, s0, 1);
        s0 += __shfl_xor_sync(0xffffffffu, s0, 2);
        s1 += __shfl_xor_sync(0xffffffffu, s1, 1);
        s1 += __shfl_xor_sync(0xffffffffu, s1, 2);
        l0 = l0 * corr0 + s0;
        l1 = l1 * corr1 + s1;
#pragma unroll
        for (int nf = 0; nf < 8; nf++) {
            oacc[nf][0] *= corr0; oacc[nf][1] *= corr0;
            oacc[nf][2] *= corr1; oacc[nf][3] *= corr1;
        }

        // ---- pack P register-direct: QK C-frag layout == PV A-frag layout ----
        uint32_t pf[4][4];
#pragma unroll
        for (int ks = 0; ks < 4; ks++) {
            pf[ks][0] = packh2(sacc[2 * ks][0], sacc[2 * ks][1]);
            pf[ks][1] = packh2(sacc[2 * ks][2], sacc[2 * ks][3]);
            pf[ks][2] = packh2(sacc[2 * ks + 1][0], sacc[2 * ks + 1][1]);
            pf[ks][3] = packh2(sacc[2 * ks + 1][2], sacc[2 * ks + 1][3]);
        }

        // ---- O += P V (pipelined vfr) ----
        {
            uint32_t vfr[2][4];
            ldm_x4(vfr[0], vAddr);
#pragma unroll
            for (int idx = 0; idx < 16; idx++) {
                const int ks = idx >> 2, np = idx & 3;
                if (idx < 15) {
                    const int nks = (idx + 1) >> 2, nnp = (idx + 1) & 3;
                    ldm_x4(vfr[(idx + 1) & 1],
                           vAddr + (uint32_t)(nnp * 16 * 144) + nks * 32);
                }
                mma_f16(oacc[2 * np], pf[ks], vfr[idx & 1]);
                mma_f16(oacc[2 * np + 1], pf[ks], vfr[idx & 1] + 2);
            }
        }

        __syncthreads();
        if (kt + 2 < S_LEN / 64) LOAD_KV(kt + 2, kt & 1);
        asm volatile("cp.async.commit_group;");
    }

    // ---- epilogue: fp16 out for the out-projection ----
    const float inv0 = 1.0f / l0;
    const float inv1 = 1.0f / l1;
    const int row0 = q0 + wid * 16 + g;
    __half* od = outp + (size_t)(b * S_LEN + row0) * HID + h * DH;
#pragma unroll
    for (int nf = 0; nf < 8; nf++) {
        const int col = nf * 8 + 2 * tig;
        *(__half2*)(od + col) =
            __floats2half2_rn(oacc[nf][0] * inv0, oacc[nf][1] * inv0);
        *(__half2*)(od + (size_t)8 * HID + col) =
            __floats2half2_rn(oacc[nf][2] * inv1, oacc[nf][3] * inv1);
    }
}

// ---------------------------------------------------------------------------
// Launch
// ---------------------------------------------------------------------------
extern "C" void kernel_launch(void* const* d_in, const int* in_sizes, int n_in,
                              void* d_out, int out_size)
{
    const float* x     = (const float*)d_in[0];
    const float* w_qkv = (const float*)d_in[1];
    const float* w_out = (const float*)d_in[2];
    const float* b_out = (const float*)d_in[3];
    float* out = (float*)d_out;

    __half *qkv_p, *vt_p, *att_p, *x_p, *wqkv_p, *wout_p;
    cudaGetSymbolAddress((void**)&qkv_p, g_qkv_h);
    cudaGetSymbolAddress((void**)&vt_p, g_vt_h);
    cudaGetSymbolAddress((void**)&att_p, g_att_h);
    cudaGetSymbolAddress((void**)&x_p, g_x_h);
    cudaGetSymbolAddress((void**)&wqkv_p, g_wqkv_h);
    cudaGetSymbolAddress((void**)&wout_p, g_wout_h);

    const int gemm_smem = NSTAGE * 2 * STAGEH * 2;  // 110592 bytes
    cudaFuncSetAttribute(gemm_h_kernel,
                         cudaFuncAttributeMaxDynamicSharedMemorySize, gemm_smem);
    cudaFuncSetAttribute(attn_h_kernel,
                         cudaFuncAttributeMaxDynamicSharedMemorySize, SMEM_ATT);

    // 0) fused fp32 -> fp16 conversion
    conv_all_kernel<<<(NX + NWQ + NWO) / 4 / 256, 256>>>(
        x, w_qkv, w_out, x_p, wqkv_p, wout_p);

    // 1) qkv = x @ w_qkv^T  (q,k -> g_qkv_h; v -> g_vt_h transposed, coalesced)
    gemm_h_kernel<<<dim3(3 * HID / BN, MTOT / BM), 256, gemm_smem>>>(
        x_p, wqkv_p, nullptr, nullptr, qkv_p, vt_p, MTOT, 3 * HID, HID, 1);

    // 2) fp16 flash attention (64q CTAs, 4/SM, register-direct P)
    attn_h_kernel<<<dim3(S_LEN / 64, BATCH * NH), 128, SMEM_ATT>>>(
        qkv_p, vt_p, att_p);

    // 3) out = att @ w_out^T + b_out  (fp32 output)
    gemm_h_kernel<<<dim3(HID / BN, MTOT / BM), 256, gemm_smem>>>(
        att_p, wout_p, b_out, out, nullptr, nullptr, MTOT, HID, HID, 0);
}